// round 13
// baseline (speedup 1.0000x reference)
#include <cuda_runtime.h>
#include <cstdint>

#define BATCH   16384
#define NF      27            // 1 dense + 26 sparse rows
#define OUTW    479           // 128 + 351
#define WPC     8             // warps (= samples) per CTA
#define THREADS 256
#define HSIZE   3456          // 27 rows x 128 B (bf16 hi)
#define WBUF    6912          // H + L, no pad rows
#define SMEM_BYTES (WPC * WBUF + 1024)   // 56320 -> 4 CTAs/SM (225 KB)

__device__ __forceinline__ uint32_t smem_u32(const void* p) {
    uint32_t a;
    asm("{ .reg .u64 t; cvta.to.shared.u64 t, %1; cvt.u32.u64 %0, t; }" : "=r"(a) : "l"(p));
    return a;
}
__device__ __forceinline__ void ldm4(uint32_t r[4], uint32_t addr) {
    asm volatile("ldmatrix.sync.aligned.m8n8.x4.shared.b16 {%0,%1,%2,%3}, [%4];"
                 : "=r"(r[0]), "=r"(r[1]), "=r"(r[2]), "=r"(r[3]) : "r"(addr));
}
__device__ __forceinline__ void mma16816(float d[4], const uint32_t a[4], const uint32_t b[2]) {
    asm volatile(
        "mma.sync.aligned.m16n8k16.row.col.f32.bf16.bf16.f32 "
        "{%0,%1,%2,%3}, {%4,%5,%6,%7}, {%8,%9}, {%0,%1,%2,%3};"
        : "+f"(d[0]), "+f"(d[1]), "+f"(d[2]), "+f"(d[3])
        : "r"(a[0]), "r"(a[1]), "r"(a[2]), "r"(a[3]), "r"(b[0]), "r"(b[1]));
}
__device__ __forceinline__ void sts2(uint32_t addr, float x, float y) {
    asm volatile("st.shared.v2.b32 [%0], {%1,%2};"
                 :: "r"(addr), "r"(__float_as_uint(x)), "r"(__float_as_uint(y)));
}
__device__ __forceinline__ float lds1(uint32_t addr) {
    float v;
    asm volatile("ld.shared.f32 %0, [%1];" : "=f"(v) : "r"(addr));
    return v;
}

// Per-warp buffer (one K-half at a time), NO pad rows:
//   H rows 0..26 (row = feature; 64 bf16 = 128 B/row) at [0, 3456)
//   L rows 0..26 at [3456, 6912)
// Swizzle: 16B chunk q of row r stored at chunk (q ^ (r & 7)) -> conflict-free ldmatrix.
// ldmatrix "rows 27-31" read adjacent finite data; any garbage (incl. NaN) there only
// pollutes G rows/cols >= 27, which the triu gather (i,j <= 26) never touches.
// Epilogue overlay: G upper-left, stride 34 floats (needs < 3700 B).

__global__ __launch_bounds__(THREADS, 4)
void dlrm_mma_kernel(const float* __restrict__ dense,
                     const float* __restrict__ sparse,
                     float* __restrict__ out) {
    extern __shared__ __align__(128) char smem[];
    const int tid  = threadIdx.x;
    const int w    = tid >> 5;
    const int lane = tid & 31;
    const int b    = blockIdx.x * WPC + w;
    const uint32_t buf = smem_u32(smem) + w * WBUF;

    // per-lane constants
    const int cl  = lane & 15, r2 = lane >> 4;              // load mapping
    const int rowA = (lane & 7) + ((lane >> 3) & 1) * 8;    // ldmatrix A row (+ mt*16)
    const int qsA  = (lane >> 4) & 1;                        // A k-chunk select
    const int rowB = (lane & 7) + ((lane >> 4) & 1) * 8;    // ldmatrix B row (+ nt*16)
    const int qsB  = (lane >> 3) & 1;

    // G upper tiles: (mt,nt) in {(0,0),(0,1),(0,2),(0,3),(1,2),(1,3)}; 16x8 each
    float acc[6][4];
#pragma unroll
    for (int t = 0; t < 6; t++)
#pragma unroll
        for (int i = 0; i < 4; i++) acc[t][i] = 0.f;

#pragma unroll
    for (int half = 0; half < 2; half++) {
        // ---- load + bf16 split (warp loads its own sample's K-half) ----
        const int gchunk = half * 16 + cl;      // float4 index within the 128-f row
#pragma unroll
        for (int it = 0; it < 14; it++) {
            const int f = it * 2 + r2;
            if (f < NF) {
                float4 v = (f == 0)
                    ? reinterpret_cast<const float4*>(dense)[b * 32 + gchunk]
                    : reinterpret_cast<const float4*>(sparse)[(b * 26 + (f - 1)) * 32 + gchunk];
                if (f == 0) {                    // dense passthrough
                    float* o = out + (size_t)b * OUTW + (gchunk << 2);
                    o[0] = v.x; o[1] = v.y; o[2] = v.z; o[3] = v.w;
                }
                uint32_t h01, h23, l01, l23;
                asm("cvt.rn.bf16x2.f32 %0, %1, %2;" : "=r"(h01) : "f"(v.y), "f"(v.x));
                asm("cvt.rn.bf16x2.f32 %0, %1, %2;" : "=r"(h23) : "f"(v.w), "f"(v.z));
                float s0 = v.x - __uint_as_float(h01 << 16);
                float s1 = v.y - __uint_as_float(h01 & 0xFFFF0000u);
                float s2 = v.z - __uint_as_float(h23 << 16);
                float s3 = v.w - __uint_as_float(h23 & 0xFFFF0000u);
                asm("cvt.rn.bf16x2.f32 %0, %1, %2;" : "=r"(l01) : "f"(s1), "f"(s0));
                asm("cvt.rn.bf16x2.f32 %0, %1, %2;" : "=r"(l23) : "f"(s3), "f"(s2));
                const uint32_t off = buf + f * 128
                                   + ((((cl >> 1) ^ (f & 7))) << 4) + ((cl & 1) << 3);
                asm volatile("st.shared.v2.b32 [%0], {%1,%2};" :: "r"(off), "r"(h01), "r"(h23));
                asm volatile("st.shared.v2.b32 [%0], {%1,%2};" :: "r"(off + HSIZE), "r"(l01), "r"(l23));
            }
        }
        __syncwarp();

        // ---- 4 K-steps of m16n8k16; G = H·H^T + H·L^T + L·H^T on upper tiles ----
        // B-frags consumed in two n-halves to cap live registers (<=64 total).
#pragma unroll
        for (int k = 0; k < 4; k++) {
            const int qA = (k * 2 + qsA) ^ (rowA & 7);
            const int qB = (k * 2 + qsB) ^ (rowB & 7);
            const uint32_t pA = buf + rowA * 128 + (qA << 4);
            const uint32_t pB = buf + rowB * 128 + (qB << 4);
            uint32_t aH0[4], aH1[4], aL0[4], aL1[4];
            ldm4(aH0, pA);           ldm4(aH1, pA + 2048);          // H (A) m 0-15 / 16-31
            ldm4(aL0, pA + HSIZE);   ldm4(aL1, pA + HSIZE + 2048);  // L (A)
            {   // n-half 0 (nt 0,1): tiles (0,0),(0,1)
                uint32_t bH[4], bL[4];
                ldm4(bH, pB);  ldm4(bL, pB + HSIZE);
                mma16816(acc[0], aH0, bH);      mma16816(acc[0], aH0, bL);      mma16816(acc[0], aL0, bH);
                mma16816(acc[1], aH0, bH + 2);  mma16816(acc[1], aH0, bL + 2);  mma16816(acc[1], aL0, bH + 2);
            }
            {   // n-half 1 (nt 2,3): tiles (0,2),(0,3),(1,2),(1,3)
                uint32_t bH[4], bL[4];
                ldm4(bH, pB + 2048);  ldm4(bL, pB + HSIZE + 2048);
                mma16816(acc[2], aH0, bH);      mma16816(acc[2], aH0, bL);      mma16816(acc[2], aL0, bH);
                mma16816(acc[3], aH0, bH + 2);  mma16816(acc[3], aH0, bL + 2);  mma16816(acc[3], aL0, bH + 2);
                mma16816(acc[4], aH1, bH);      mma16816(acc[4], aH1, bL);      mma16816(acc[4], aL1, bH);
                mma16816(acc[5], aH1, bH + 2);  mma16816(acc[5], aH1, bL + 2);  mma16816(acc[5], aL1, bH + 2);
            }
        }
        __syncwarp();
    }

    // ---- epilogue: stage 6 G tiles into dead buffer (stride 34), gather triu ----
    {
        const int rr = lane >> 2, cc = (lane & 3) * 2;
        const int pmt[6] = {0, 0, 0, 0, 1, 1};
        const int pnt[6] = {0, 1, 2, 3, 2, 3};
#pragma unroll
        for (int t = 0; t < 6; t++) {
            const uint32_t ad = buf + (((pmt[t] * 16 + rr) * 34 + pnt[t] * 8 + cc) << 2);
            sts2(ad,           acc[t][0], acc[t][1]);
            sts2(ad + 8 * 136, acc[t][2], acc[t][3]);   // +8 rows
        }
    }
    __syncwarp();

    float* orow = out + (size_t)b * OUTW + 128;
#pragma unroll
    for (int t = 0; t < 11; t++) {
        const int p = lane + t * 32;
        if (p < 351) {
            // invert p -> (i, j) of triu_indices(27, k=1): S(i) = i*(53-i)/2
            int i = (int)((53.0f - sqrtf((float)(2809 - 8 * p))) * 0.5f);
            if (i > 0 && p < (i * (53 - i)) / 2) i--;
            if (p >= ((i + 1) * (52 - i)) / 2) i++;
            const int j = i + 1 + (p - (i * (53 - i)) / 2);
            orow[p] = lds1(buf + ((i * 34 + j) << 2));
        }
    }
}

extern "C" void kernel_launch(void* const* d_in, const int* in_sizes, int n_in,
                              void* d_out, int out_size) {
    const float* dense  = (const float*)d_in[0];   // [16384, 128] fp32
    const float* sparse = (const float*)d_in[1];   // [16384, 26, 128] fp32
    float* out = (float*)d_out;                    // [16384, 479] fp32

    cudaFuncSetAttribute(dlrm_mma_kernel,
                         cudaFuncAttributeMaxDynamicSharedMemorySize, SMEM_BYTES);
    dlrm_mma_kernel<<<BATCH / WPC, THREADS, SMEM_BYTES>>>(dense, sparse, out);
}

// round 14
// speedup vs baseline: 1.1475x; 1.1475x over previous
#include <cuda_runtime.h>
#include <cstdint>

#define BATCH   16384
#define NF      27            // 1 dense + 26 sparse rows
#define OUTW    479           // 128 + 351
#define WPC     8             // warps (= samples) per CTA
#define THREADS 256
#define WBUF    8192          // bytes per warp: H[32x64bf16]=4K + L=4K (epilogue overlays)
#define SMEM_BYTES (WPC * WBUF)   // 65536 -> 3 CTAs/SM

__device__ __forceinline__ uint32_t smem_u32(const void* p) {
    uint32_t a;
    asm("{ .reg .u64 t; cvta.to.shared.u64 t, %1; cvt.u32.u64 %0, t; }" : "=r"(a) : "l"(p));
    return a;
}
__device__ __forceinline__ void ldm4(uint32_t r[4], uint32_t addr) {
    asm volatile("ldmatrix.sync.aligned.m8n8.x4.shared.b16 {%0,%1,%2,%3}, [%4];"
                 : "=r"(r[0]), "=r"(r[1]), "=r"(r[2]), "=r"(r[3]) : "r"(addr));
}
__device__ __forceinline__ void mma16816(float d[4], const uint32_t a[4], const uint32_t b[2]) {
    asm volatile(
        "mma.sync.aligned.m16n8k16.row.col.f32.bf16.bf16.f32 "
        "{%0,%1,%2,%3}, {%4,%5,%6,%7}, {%8,%9}, {%0,%1,%2,%3};"
        : "+f"(d[0]), "+f"(d[1]), "+f"(d[2]), "+f"(d[3])
        : "r"(a[0]), "r"(a[1]), "r"(a[2]), "r"(a[3]), "r"(b[0]), "r"(b[1]));
}
__device__ __forceinline__ void sts2(uint32_t addr, float x, float y) {
    asm volatile("st.shared.v2.b32 [%0], {%1,%2};"
                 :: "r"(addr), "r"(__float_as_uint(x)), "r"(__float_as_uint(y)));
}
__device__ __forceinline__ float lds1(uint32_t addr) {
    float v;
    asm volatile("ld.shared.f32 %0, [%1];" : "=f"(v) : "r"(addr));
    return v;
}

// Per-warp buffer (one K-half at a time):
//   H rows 0..31 (row = feature; 64 bf16 = 128 B/row) at [0, 4096)
//   L rows 0..31 at [4096, 8192)
// Swizzle: 16B chunk q of row r stored at chunk (q ^ (r & 7)) -> conflict-free ldmatrix.
// Rows 27-31 hold stale data; they only pollute G rows/cols >= 27, never read.
// Epilogue overlay: G upper-left, stride 34 floats, at [0, 4352).

// global row load: f = feature row, gchunk = float4 index within the 128-float row
__device__ __forceinline__ float4 ldrow(const float* __restrict__ dense,
                                        const float* __restrict__ sparse,
                                        int b, int f, int gchunk) {
    if (f == 0)
        return reinterpret_cast<const float4*>(dense)[b * 32 + gchunk];
    if (f < NF)
        return reinterpret_cast<const float4*>(sparse)[(b * 26 + (f - 1)) * 32 + gchunk];
    return make_float4(0.f, 0.f, 0.f, 0.f);
}

// bf16 hi/lo split + swizzled store into H/L
__device__ __forceinline__ void cvstore(uint32_t buf, int f, int cl, float4 v) {
    uint32_t h01, h23, l01, l23;
    asm("cvt.rn.bf16x2.f32 %0, %1, %2;" : "=r"(h01) : "f"(v.y), "f"(v.x));
    asm("cvt.rn.bf16x2.f32 %0, %1, %2;" : "=r"(h23) : "f"(v.w), "f"(v.z));
    float s0 = v.x - __uint_as_float(h01 << 16);
    float s1 = v.y - __uint_as_float(h01 & 0xFFFF0000u);
    float s2 = v.z - __uint_as_float(h23 << 16);
    float s3 = v.w - __uint_as_float(h23 & 0xFFFF0000u);
    asm("cvt.rn.bf16x2.f32 %0, %1, %2;" : "=r"(l01) : "f"(s1), "f"(s0));
    asm("cvt.rn.bf16x2.f32 %0, %1, %2;" : "=r"(l23) : "f"(s3), "f"(s2));
    const uint32_t off = buf + f * 128 + ((((cl >> 1) ^ (f & 7))) << 4) + ((cl & 1) << 3);
    asm volatile("st.shared.v2.b32 [%0], {%1,%2};" :: "r"(off), "r"(h01), "r"(h23));
    asm volatile("st.shared.v2.b32 [%0], {%1,%2};" :: "r"(off + 4096), "r"(l01), "r"(l23));
}

__global__ __launch_bounds__(THREADS, 3)
void dlrm_mma_kernel(const float* __restrict__ dense,
                     const float* __restrict__ sparse,
                     float* __restrict__ out) {
    extern __shared__ __align__(128) char smem[];
    const int tid  = threadIdx.x;
    const int w    = tid >> 5;
    const int lane = tid & 31;
    const int b    = blockIdx.x * WPC + w;
    const uint32_t buf = smem_u32(smem) + w * WBUF;

    const int cl  = lane & 15, r2 = lane >> 4;              // load mapping
    const int rowA = (lane & 7) + ((lane >> 3) & 1) * 8;    // ldmatrix A row (+ mt*16)
    const int qsA  = (lane >> 4) & 1;
    const int rowB = (lane & 7) + ((lane >> 4) & 1) * 8;    // ldmatrix B row (+ nt*16)
    const int qsB  = (lane >> 3) & 1;

    // ---- half-0 load: batch ALL 14 LDG.128 first (max MLP), then convert ----
    float4 v0[14];
#pragma unroll
    for (int it = 0; it < 14; it++)
        v0[it] = ldrow(dense, sparse, b, 2 * it + r2, cl);
    if (r2 == 0) {                       // dense passthrough, half-0 chunks
        float* o = out + (size_t)b * OUTW + (cl << 2);
        o[0] = v0[0].x; o[1] = v0[0].y; o[2] = v0[0].z; o[3] = v0[0].w;
    }
#pragma unroll
    for (int it = 0; it < 14; it++) {
        const int f = 2 * it + r2;
        if (f < NF) cvstore(buf, f, cl, v0[it]);
    }
    __syncwarp();

    // ---- prefetch half-1 part A (7 LDGs) before compute; streams during MMAs ----
    float4 v1[7];
#pragma unroll
    for (int it = 0; it < 7; it++)
        v1[it] = ldrow(dense, sparse, b, 2 * it + r2, 16 + cl);

    // G upper tiles: (mt,nt) in {(0,0),(0,1),(0,2),(0,3),(1,2),(1,3)}; 16x8 each
    float acc[6][4];
#pragma unroll
    for (int t = 0; t < 6; t++)
#pragma unroll
        for (int i = 0; i < 4; i++) acc[t][i] = 0.f;

    // ---- compute + half-1 load/convert ----
#pragma unroll
    for (int half = 0; half < 2; half++) {
        // 4 K-steps of m16n8k16; G = H·H^T + H·L^T + L·H^T on upper tiles
#pragma unroll
        for (int k = 0; k < 4; k++) {
            const int qA = (k * 2 + qsA) ^ (rowA & 7);
            const int qB = (k * 2 + qsB) ^ (rowB & 7);
            const uint32_t pA = buf + rowA * 128 + (qA << 4);
            const uint32_t pB = buf + rowB * 128 + (qB << 4);
            uint32_t aH0[4], aH1[4], aL0[4], aL1[4];
            uint32_t bH0[4], bH1[4], bL0[4], bL1[4];
            ldm4(aH0, pA);          ldm4(aH1, pA + 2048);
            ldm4(aL0, pA + 4096);   ldm4(aL1, pA + 6144);
            ldm4(bH0, pB);          ldm4(bH1, pB + 2048);
            ldm4(bL0, pB + 4096);   ldm4(bL1, pB + 6144);
            mma16816(acc[0], aH0, bH0);      mma16816(acc[0], aH0, bL0);      mma16816(acc[0], aL0, bH0);
            mma16816(acc[1], aH0, bH0 + 2);  mma16816(acc[1], aH0, bL0 + 2);  mma16816(acc[1], aL0, bH0 + 2);
            mma16816(acc[2], aH0, bH1);      mma16816(acc[2], aH0, bL1);      mma16816(acc[2], aL0, bH1);
            mma16816(acc[3], aH0, bH1 + 2);  mma16816(acc[3], aH0, bL1 + 2);  mma16816(acc[3], aL0, bH1 + 2);
            mma16816(acc[4], aH1, bH1);      mma16816(acc[4], aH1, bL1);      mma16816(acc[4], aL1, bH1);
            mma16816(acc[5], aH1, bH1 + 2);  mma16816(acc[5], aH1, bL1 + 2);  mma16816(acc[5], aL1, bH1 + 2);
        }
        __syncwarp();

        if (half == 0) {
            // store the prefetched half-1 part A, then load+convert part B
            if (r2 == 0) {               // dense passthrough, half-1 chunks
                float* o = out + (size_t)b * OUTW + ((16 + cl) << 2);
                o[0] = v1[0].x; o[1] = v1[0].y; o[2] = v1[0].z; o[3] = v1[0].w;
            }
#pragma unroll
            for (int it = 0; it < 7; it++) {
                const int f = 2 * it + r2;
                if (f < NF) cvstore(buf, f, cl, v1[it]);
            }
            float4 vb[7];
#pragma unroll
            for (int it = 7; it < 14; it++)
                vb[it - 7] = ldrow(dense, sparse, b, 2 * it + r2, 16 + cl);
#pragma unroll
            for (int it = 7; it < 14; it++) {
                const int f = 2 * it + r2;
                if (f < NF) cvstore(buf, f, cl, vb[it - 7]);
            }
            __syncwarp();
        }
    }

    // ---- epilogue: stage 6 G tiles into dead buffer (stride 34), gather triu ----
    {
        const int rr = lane >> 2, cc = (lane & 3) * 2;
        const int pmt[6] = {0, 0, 0, 0, 1, 1};
        const int pnt[6] = {0, 1, 2, 3, 2, 3};
#pragma unroll
        for (int t = 0; t < 6; t++) {
            const uint32_t ad = buf + (((pmt[t] * 16 + rr) * 34 + pnt[t] * 8 + cc) << 2);
            sts2(ad,           acc[t][0], acc[t][1]);
            sts2(ad + 8 * 136, acc[t][2], acc[t][3]);   // +8 rows
        }
    }
    __syncwarp();

    float* orow = out + (size_t)b * OUTW + 128;
#pragma unroll
    for (int t = 0; t < 11; t++) {
        const int p = lane + t * 32;
        if (p < 351) {
            // invert p -> (i, j) of triu_indices(27, k=1): S(i) = i*(53-i)/2
            int i = (int)((53.0f - sqrtf((float)(2809 - 8 * p))) * 0.5f);
            if (i > 0 && p < (i * (53 - i)) / 2) i--;
            if (p >= ((i + 1) * (52 - i)) / 2) i++;
            const int j = i + 1 + (p - (i * (53 - i)) / 2);
            orow[p] = lds1(buf + ((i * 34 + j) << 2));
        }
    }
}

extern "C" void kernel_launch(void* const* d_in, const int* in_sizes, int n_in,
                              void* d_out, int out_size) {
    const float* dense  = (const float*)d_in[0];   // [16384, 128] fp32
    const float* sparse = (const float*)d_in[1];   // [16384, 26, 128] fp32
    float* out = (float*)d_out;                    // [16384, 479] fp32

    cudaFuncSetAttribute(dlrm_mma_kernel,
                         cudaFuncAttributeMaxDynamicSharedMemorySize, SMEM_BYTES);
    dlrm_mma_kernel<<<BATCH / WPC, THREADS, SMEM_BYTES>>>(dense, sparse, out);
}